// round 2
// baseline (speedup 1.0000x reference)
#include <cuda_runtime.h>
#include <cuda_bf16.h>
#include <math.h>

// ---------------------------------------------------------------------------
// Problem: AFNO2D block.  x:(1,768,256,512) fp32.
// out = x + irfft2_ortho( softshrink( W2*relu(W1*rfft2_ortho(x)[:,:, :, :129] + b1) + b2 ) )
// 8 blocks of 96 channels; per-mode 96x96 complex MLP.
// ---------------------------------------------------------------------------

#define CN 768
#define HN 256
#define WN 512
#define WC 129
#define MODES (HN * WC)          // 33024
#define NROWS (CN * HN)          // 196608
#define FWD_SCALE 0.00276213586400995f   // 1/sqrt(256*512)
#define INV_SCALE 0.00552427172801990f   // sqrt(2)/256
#define LAMBDA 0.01f
#define TWO_PI 6.283185307179586f

// scratch spectrum [c][h][y] complex fp32  (~203 MB)
__device__ float2 g_spec[(size_t)CN * MODES];

__device__ __forceinline__ float2 cadd(float2 a, float2 b) { return make_float2(a.x + b.x, a.y + b.y); }
__device__ __forceinline__ float2 csub(float2 a, float2 b) { return make_float2(a.x - b.x, a.y - b.y); }
__device__ __forceinline__ float2 cmul(float2 a, float2 b) { return make_float2(a.x * b.x - a.y * b.y, a.x * b.y + a.y * b.x); }
__device__ __forceinline__ float2 conjf2(float2 a) { return make_float2(a.x, -a.y); }

// ---------------------------------------------------------------------------
// Kernel 1: forward real FFT along W (512) via 256-pt complex pack trick.
// One row per CTA, 128 threads. Stockham autosort, 8 radix-2 stages.
// Writes UNNORMALIZED X[0..128] to g_spec (ortho scale applied in k_fft_h).
// ---------------------------------------------------------------------------
__global__ void k_fwd_w(const float* __restrict__ x) {
    __shared__ float2 bufA[256];
    __shared__ float2 bufB[256];
    __shared__ float2 tw[128];
    const int t = threadIdx.x;
    {
        float s, c;
        sincosf(-TWO_PI * (float)t / 256.0f, &s, &c);
        tw[t] = make_float2(c, s);
    }
    const size_t row = blockIdx.x;
    const float2* xr = reinterpret_cast<const float2*>(x) + row * 256;
    bufA[t] = xr[t];            // z[n] = x[2n] + i x[2n+1]
    bufA[t + 128] = xr[t + 128];
    __syncthreads();

    float2* S = bufA;
    float2* D = bufB;
#pragma unroll
    for (int st = 0; st < 8; st++) {
        const int q = t & ((1 << st) - 1);
        const float2 w = tw[t - q];
        const float2 a = S[t];
        const float2 b = S[t + 128];
        D[2 * t - q] = cadd(a, b);
        D[2 * t - q + (1 << st)] = cmul(csub(a, b), w);
        __syncthreads();
        float2* tmp = S; S = D; D = tmp;
    }
    // S == bufA (8 swaps). Hermitian unpack: X[k] = 0.5(Z[k]+conj(Z[256-k])) - 0.5 i e^{-2pi i k/512}(Z[k]-conj(Z[256-k]))
    float2* dst = g_spec + row * WC;
    {
        const float2 Zk = S[t];
        const float2 Zc = conjf2(S[(256 - t) & 255]);
        float s5, c5;
        sincosf(-TWO_PI * (float)t / 512.0f, &s5, &c5);
        const float2 ed = cmul(make_float2(c5, s5), csub(Zk, Zc));
        const float2 sm = cadd(Zk, Zc);
        dst[t] = make_float2(0.5f * (sm.x + ed.y), 0.5f * (sm.y - ed.x));
    }
    if (t == 0) {
        // k = 128: e^{-2pi i*128/512} = -i
        const float2 Zk = S[128];
        const float2 Zc = conjf2(S[128]);
        const float2 ed = cmul(make_float2(0.f, -1.f), csub(Zk, Zc));
        const float2 sm = cadd(Zk, Zc);
        dst[128] = make_float2(0.5f * (sm.x + ed.y), 0.5f * (sm.y - ed.x));
    }
}

// ---------------------------------------------------------------------------
// Kernels 2/4: 256-pt complex FFT along H over columns of g_spec.
// SIGN=-1 forward (scale=FWD_SCALE), SIGN=+1 inverse (scale=1, unnormalized).
// CTA: 256 threads, 8 columns of one channel, smem-transposed.
// ---------------------------------------------------------------------------
template <int SIGN>
__global__ void k_fft_h(float scale) {
    __shared__ float2 b0[8][257];
    __shared__ float2 b1s[8][257];
    __shared__ float2 tw[128];
    const int tid = threadIdx.x;
    if (tid < 128) {
        float s, c;
        sincosf((float)SIGN * TWO_PI * (float)tid / 256.0f, &s, &c);
        tw[tid] = make_float2(c, s);
    }
    const int ch = blockIdx.y;
    const int y0 = blockIdx.x * 8;
    const int yc = tid & 7;
    const int hh = tid >> 3;   // 0..31
    const int y = y0 + yc;
    {
#pragma unroll
        for (int i = 0; i < 8; i++) {
            const int h = hh + i * 32;
            float2 v = make_float2(0.f, 0.f);
            if (y < WC) v = g_spec[((size_t)ch * HN + h) * WC + y];
            b0[yc][h] = v;
        }
    }
    __syncthreads();

    float2(*S)[257] = b0;
    float2(*D)[257] = b1s;
#pragma unroll
    for (int st = 0; st < 8; st++) {
#pragma unroll
        for (int i = 0; i < 4; i++) {
            const int idx = tid + (i << 8);     // 0..1023
            const int col = idx >> 7;           // 0..7
            const int t = idx & 127;
            const int q = t & ((1 << st) - 1);
            const float2 w = tw[t - q];
            const float2 a = S[col][t];
            const float2 b = S[col][t + 128];
            D[col][2 * t - q] = cadd(a, b);
            D[col][2 * t - q + (1 << st)] = cmul(csub(a, b), w);
        }
        __syncthreads();
        float2(*tmp)[257] = S; S = D; D = tmp;
    }
    if (y < WC) {
#pragma unroll
        for (int i = 0; i < 8; i++) {
            const int h = hh + i * 32;
            const float2 v = S[yc][h];
            g_spec[((size_t)ch * HN + h) * WC + y] = make_float2(v.x * scale, v.y * scale);
        }
    }
}

// ---------------------------------------------------------------------------
// Kernel 3: per-block complex MLP over 32-mode tiles, in place on g_spec.
// grid (1032, 8), 256 threads, 194 KB dynamic smem.
// ---------------------------------------------------------------------------
__global__ void k_mlp(const float* __restrict__ w1, const float* __restrict__ b1,
                      const float* __restrict__ w2, const float* __restrict__ b2) {
    extern __shared__ float2 sm[];
    float2* sW1 = sm;            // 9216  [i*96+o]
    float2* sW2 = sW1 + 9216;    // 9216
    float2* sA  = sW2 + 9216;    // 3072  [i*32+j]
    float2* sO  = sA + 3072;     // 3072
    float2* sB1 = sO + 3072;     // 96
    float2* sB2 = sB1 + 96;      // 96

    const int tid = threadIdx.x;
    const int k = blockIdx.y;
    const size_t m0 = (size_t)blockIdx.x * 32;

    // load weights (float4 vectorized) + biases
    {
        const float4* gw1 = reinterpret_cast<const float4*>(w1) + (size_t)k * 4608;
        const float4* gw2 = reinterpret_cast<const float4*>(w2) + (size_t)k * 4608;
        float4* s1 = reinterpret_cast<float4*>(sW1);
        float4* s2 = reinterpret_cast<float4*>(sW2);
        for (int i = tid; i < 4608; i += 256) s1[i] = gw1[i];
        for (int i = tid; i < 4608; i += 256) s2[i] = gw2[i];
        if (tid < 96) {
            sB1[tid] = reinterpret_cast<const float2*>(b1)[k * 96 + tid];
            sB2[tid] = reinterpret_cast<const float2*>(b2)[k * 96 + tid];
        }
    }
    // load activation tile: 96 channels x 32 modes
    for (int idx = tid; idx < 3072; idx += 256) {
        const int i = idx >> 5;
        const int j = idx & 31;
        sA[idx] = g_spec[((size_t)(k * 96 + i)) * MODES + m0 + j];
    }
    __syncthreads();

    const int j = tid & 31;
    const int wrp = tid >> 5;
    const float4* W1_4 = reinterpret_cast<const float4*>(sW1);
    const float4* W2_4 = reinterpret_cast<const float4*>(sW2);

    // ---- layer 1: t1 = a*W1 + b1, relu on both parts ----
#pragma unroll
    for (int p = 0; p < 3; p++) {
        const int och = ((p * 8 + wrp) << 2);   // 0..92 step 4
        float2 a0 = sB1[och], a1 = sB1[och + 1], a2 = sB1[och + 2], a3 = sB1[och + 3];
        const int wb = och >> 1;
        const float2* ap = sA + j;
#pragma unroll 8
        for (int i = 0; i < 96; i++) {
            const float2 a = ap[i * 32];
            const float4 wA = W1_4[wb + i * 48];
            const float4 wB = W1_4[wb + i * 48 + 1];
            a0.x += a.x * wA.x - a.y * wA.y; a0.y += a.x * wA.y + a.y * wA.x;
            a1.x += a.x * wA.z - a.y * wA.w; a1.y += a.x * wA.w + a.y * wA.z;
            a2.x += a.x * wB.x - a.y * wB.y; a2.y += a.x * wB.y + a.y * wB.x;
            a3.x += a.x * wB.z - a.y * wB.w; a3.y += a.x * wB.w + a.y * wB.z;
        }
        a0.x = fmaxf(a0.x, 0.f); a0.y = fmaxf(a0.y, 0.f);
        a1.x = fmaxf(a1.x, 0.f); a1.y = fmaxf(a1.y, 0.f);
        a2.x = fmaxf(a2.x, 0.f); a2.y = fmaxf(a2.y, 0.f);
        a3.x = fmaxf(a3.x, 0.f); a3.y = fmaxf(a3.y, 0.f);
        sO[(och + 0) * 32 + j] = a0;
        sO[(och + 1) * 32 + j] = a1;
        sO[(och + 2) * 32 + j] = a2;
        sO[(och + 3) * 32 + j] = a3;
    }
    __syncthreads();

    // ---- layer 2: t2 = o1*W2 + b2, softshrink, store ----
#pragma unroll
    for (int p = 0; p < 3; p++) {
        const int och = ((p * 8 + wrp) << 2);
        float2 a0 = sB2[och], a1 = sB2[och + 1], a2 = sB2[och + 2], a3 = sB2[och + 3];
        const int wb = och >> 1;
        const float2* ap = sO + j;
#pragma unroll 8
        for (int i = 0; i < 96; i++) {
            const float2 a = ap[i * 32];
            const float4 wA = W2_4[wb + i * 48];
            const float4 wB = W2_4[wb + i * 48 + 1];
            a0.x += a.x * wA.x - a.y * wA.y; a0.y += a.x * wA.y + a.y * wA.x;
            a1.x += a.x * wA.z - a.y * wA.w; a1.y += a.x * wA.w + a.y * wA.z;
            a2.x += a.x * wB.x - a.y * wB.y; a2.y += a.x * wB.y + a.y * wB.x;
            a3.x += a.x * wB.z - a.y * wB.w; a3.y += a.x * wB.w + a.y * wB.z;
        }
        a0.x = copysignf(fmaxf(fabsf(a0.x) - LAMBDA, 0.f), a0.x);
        a0.y = copysignf(fmaxf(fabsf(a0.y) - LAMBDA, 0.f), a0.y);
        a1.x = copysignf(fmaxf(fabsf(a1.x) - LAMBDA, 0.f), a1.x);
        a1.y = copysignf(fmaxf(fabsf(a1.y) - LAMBDA, 0.f), a1.y);
        a2.x = copysignf(fmaxf(fabsf(a2.x) - LAMBDA, 0.f), a2.x);
        a2.y = copysignf(fmaxf(fabsf(a2.y) - LAMBDA, 0.f), a2.y);
        a3.x = copysignf(fmaxf(fabsf(a3.x) - LAMBDA, 0.f), a3.x);
        a3.y = copysignf(fmaxf(fabsf(a3.y) - LAMBDA, 0.f), a3.y);
        g_spec[((size_t)(k * 96 + och + 0)) * MODES + m0 + j] = a0;
        g_spec[((size_t)(k * 96 + och + 1)) * MODES + m0 + j] = a1;
        g_spec[((size_t)(k * 96 + och + 2)) * MODES + m0 + j] = a2;
        g_spec[((size_t)(k * 96 + och + 3)) * MODES + m0 + j] = a3;
    }
}

// ---------------------------------------------------------------------------
// Kernel 5: inverse real FFT along W. Given X[0..128] (X[129..256]=0, Im X[0]
// dropped per c2r convention), build packed 256-bin spectrum Zf, inverse
// 256-pt Stockham (e^{+}), scale sqrt(2)/256, add residual x, write out.
// ---------------------------------------------------------------------------
__global__ void k_inv_w(const float* __restrict__ x, float* __restrict__ out) {
    __shared__ float2 sX[257];
    __shared__ float2 bufA[256];
    __shared__ float2 bufB[256];
    __shared__ float2 tw[128];
    const int t = threadIdx.x;  // 128
    {
        float s, c;
        sincosf(TWO_PI * (float)t / 256.0f, &s, &c);
        tw[t] = make_float2(c, s);
    }
    const size_t row = blockIdx.x;
    const float2* src = g_spec + row * WC;
    {
        float2 v = src[t];
        if (t == 0) v.y = 0.f;      // c2r ignores Im of bin 0
        sX[t] = v;
        sX[129 + t] = make_float2(0.f, 0.f);   // bins 129..256 zero
        if (t == 0) sX[128] = src[128];
    }
    __syncthreads();
    // Zf[k] = E[k] + i O[k]; E = 0.5(X[k]+conj(X[256-k])); O = e^{+2pi i k/512} * 0.5(X[k]-conj(X[256-k]))
#pragma unroll
    for (int half = 0; half < 2; half++) {
        const int kk = t + half * 128;
        const float2 Xk = sX[kk];
        const float2 Xc = conjf2(sX[256 - kk]);
        const float2 E = make_float2(0.5f * (Xk.x + Xc.x), 0.5f * (Xk.y + Xc.y));
        const float2 Dd = make_float2(0.5f * (Xk.x - Xc.x), 0.5f * (Xk.y - Xc.y));
        float s5, c5;
        sincosf(TWO_PI * (float)kk / 512.0f, &s5, &c5);
        const float2 O = cmul(make_float2(c5, s5), Dd);
        bufA[kk] = make_float2(E.x - O.y, E.y + O.x);
    }
    __syncthreads();

    float2* S = bufA;
    float2* D = bufB;
#pragma unroll
    for (int st = 0; st < 8; st++) {
        const int q = t & ((1 << st) - 1);
        const float2 w = tw[t - q];
        const float2 a = S[t];
        const float2 b = S[t + 128];
        D[2 * t - q] = cadd(a, b);
        D[2 * t - q + (1 << st)] = cmul(csub(a, b), w);
        __syncthreads();
        float2* tmp = S; S = D; D = tmp;
    }
    // S = bufA; z[n] holds (out[2n], out[2n+1]) before scale/residual
    const float2* xr = reinterpret_cast<const float2*>(x) + row * 256;
    float2* orow = reinterpret_cast<float2*>(out) + row * 256;
    {
        const float2 z0 = S[t];
        const float2 r0 = xr[t];
        orow[t] = make_float2(z0.x * INV_SCALE + r0.x, z0.y * INV_SCALE + r0.y);
        const float2 z1 = S[t + 128];
        const float2 r1 = xr[t + 128];
        orow[t + 128] = make_float2(z1.x * INV_SCALE + r1.x, z1.y * INV_SCALE + r1.y);
    }
}

// ---------------------------------------------------------------------------
extern "C" void kernel_launch(void* const* d_in, const int* in_sizes, int n_in,
                              void* d_out, int out_size) {
    (void)in_sizes; (void)n_in; (void)out_size;
    const float* x  = (const float*)d_in[0];
    const float* w1 = (const float*)d_in[1];
    const float* b1 = (const float*)d_in[2];
    const float* w2 = (const float*)d_in[3];
    const float* b2 = (const float*)d_in[4];
    float* out = (float*)d_out;

    const int mlp_smem = (9216 * 2 + 3072 * 2 + 96 * 2) * (int)sizeof(float2);  // 198144
    cudaFuncSetAttribute(k_mlp, cudaFuncAttributeMaxDynamicSharedMemorySize, mlp_smem);

    k_fwd_w<<<NROWS, 128>>>(x);

    dim3 gh(17, CN);
    k_fft_h<-1><<<gh, 256>>>(FWD_SCALE);

    dim3 gm(MODES / 32, 8);
    k_mlp<<<gm, 256, mlp_smem>>>(w1, b1, w2, b2);

    k_fft_h<1><<<gh, 256>>>(1.0f);

    k_inv_w<<<NROWS, 128>>>(x, out);
}

// round 5
// speedup vs baseline: 2.1504x; 2.1504x over previous
#include <cuda_runtime.h>
#include <cuda_bf16.h>
#include <math.h>
#include <stdint.h>

static constexpr int kCN = 768;
static constexpr int kHN = 256;
static constexpr int kWC = 129;
static constexpr int kModes = kHN * kWC;      // 33024
static constexpr int kNRows = kCN * kHN;      // 196608
static constexpr float kFwdScale = 0.00276213586400995f;  // 1/sqrt(256*512)
static constexpr float kInvScale = 0.00552427172801990f;  // sqrt(2)/256
static constexpr float kLam = 0.01f;
static constexpr float kTwoPi = 6.283185307179586f;

__device__ float2 g_spec[(size_t)kCN * kModes];
__device__ __nv_bfloat16 g_wexp[8][2][192][192];

__device__ __forceinline__ float2 cadd(float2 a, float2 b) { return make_float2(a.x + b.x, a.y + b.y); }
__device__ __forceinline__ float2 csub(float2 a, float2 b) { return make_float2(a.x - b.x, a.y - b.y); }
__device__ __forceinline__ float2 cmul(float2 a, float2 b) { return make_float2(a.x * b.x - a.y * b.y, a.x * b.y + a.y * b.x); }

// ---- weight expansion: complex w -> real 2x2 blocks, transposed [n][k] ----
__global__ void k_prep(const float* __restrict__ w1, const float* __restrict__ w2) {
    const int idx = blockIdx.x * 256 + threadIdx.x;  // (k*96+i)*96+o
    if (idx >= 8 * 96 * 96) return;
    const int kb = idx / 9216;
    const int rr = idx % 9216;
    const int ci = rr / 96;
    const int co = rr % 96;
    for (int L = 0; L < 2; L++) {
        const float* w = (L == 0) ? w1 : w2;
        const float re = w[idx * 2];
        const float im = w[idx * 2 + 1];
        __nv_bfloat16* W = &g_wexp[kb][L][0][0];
        W[(2 * co) * 192 + 2 * ci]         = __float2bfloat16(re);
        W[(2 * co) * 192 + 2 * ci + 1]     = __float2bfloat16(-im);
        W[(2 * co + 1) * 192 + 2 * ci]     = __float2bfloat16(im);
        W[(2 * co + 1) * 192 + 2 * ci + 1] = __float2bfloat16(re);
    }
}

// ---- forward real FFT along W (512) via 256-pt pack trick ----
__global__ void k_fwd_w(const float* __restrict__ x) {
    __shared__ float2 fwA[256];
    __shared__ float2 fwB[256];
    __shared__ float2 fwT[128];
    const int t = threadIdx.x;
    {
        float s, c;
        sincosf(-kTwoPi * (float)t / 256.0f, &s, &c);
        fwT[t] = make_float2(c, s);
    }
    const size_t row = blockIdx.x;
    const float2* xr = reinterpret_cast<const float2*>(x) + row * 256;
    fwA[t] = xr[t];
    fwA[t + 128] = xr[t + 128];
    __syncthreads();

    float2* S = fwA;
    float2* D = fwB;
    for (int st = 0; st < 8; st++) {
        const int q = t & ((1 << st) - 1);
        const float2 w = fwT[t - q];
        const float2 a = S[t];
        const float2 b = S[t + 128];
        D[2 * t - q] = cadd(a, b);
        D[2 * t - q + (1 << st)] = cmul(csub(a, b), w);
        __syncthreads();
        float2* tmp = S; S = D; D = tmp;
    }
    float2* dst = g_spec + row * kWC;
    {
        const float2 Zk = S[t];
        const float2 Zr = S[(256 - t) & 255];
        const float2 Zc = make_float2(Zr.x, -Zr.y);
        float s5, c5;
        sincosf(-kTwoPi * (float)t / 512.0f, &s5, &c5);
        const float2 ed = cmul(make_float2(c5, s5), csub(Zk, Zc));
        const float2 su = cadd(Zk, Zc);
        dst[t] = make_float2(0.5f * (su.x + ed.y), 0.5f * (su.y - ed.x));
    }
    if (t == 0) {
        const float2 Zk = S[128];
        const float2 Zc = make_float2(Zk.x, -Zk.y);
        const float2 ed = cmul(make_float2(0.f, -1.f), csub(Zk, Zc));
        const float2 su = cadd(Zk, Zc);
        dst[128] = make_float2(0.5f * (su.x + ed.y), 0.5f * (su.y - ed.x));
    }
}

// ---- 256-pt complex FFT along H over columns of g_spec ----
template <int SIGN>
__global__ void k_fft_h(float scale) {
    __shared__ float2 hA[8][257];
    __shared__ float2 hB[8][257];
    __shared__ float2 hT[128];
    const int tid = threadIdx.x;
    if (tid < 128) {
        float s, c;
        sincosf((float)SIGN * kTwoPi * (float)tid / 256.0f, &s, &c);
        hT[tid] = make_float2(c, s);
    }
    const int ch = blockIdx.y;
    const int y0 = blockIdx.x * 8;
    const int yc = tid & 7;
    const int hh = tid >> 3;
    const int y = y0 + yc;
    for (int i = 0; i < 8; i++) {
        const int h = hh + i * 32;
        float2 v = make_float2(0.f, 0.f);
        if (y < kWC) v = g_spec[((size_t)ch * kHN + h) * kWC + y];
        hA[yc][h] = v;
    }
    __syncthreads();

    float2(*S)[257] = hA;
    float2(*D)[257] = hB;
    for (int st = 0; st < 8; st++) {
        for (int i = 0; i < 4; i++) {
            const int idx = tid + (i << 8);
            const int col = idx >> 7;
            const int t = idx & 127;
            const int q = t & ((1 << st) - 1);
            const float2 w = hT[t - q];
            const float2 a = S[col][t];
            const float2 b = S[col][t + 128];
            D[col][2 * t - q] = cadd(a, b);
            D[col][2 * t - q + (1 << st)] = cmul(csub(a, b), w);
        }
        __syncthreads();
        float2(*tmp)[257] = S; S = D; D = tmp;
    }
    if (y < kWC) {
        for (int i = 0; i < 8; i++) {
            const int h = hh + i * 32;
            const float2 v = S[yc][h];
            g_spec[((size_t)ch * kHN + h) * kWC + y] = make_float2(v.x * scale, v.y * scale);
        }
    }
}

// ---- tensor-core MLP ----
static constexpr int kRowB = 400;            // smem row pitch (bytes)
static constexpr int kSmA = 0;               // 128 rows * 400
static constexpr int kSmO = 51200;           // 128 rows * 400
static constexpr int kSmW = 102400;          // 192 rows * 400
static constexpr int kSmB1 = 179200;
static constexpr int kSmB2 = 179968;
static constexpr int kSmTotal = 180736;

__device__ __forceinline__ void ldsm_x4(uint32_t* r, uint32_t addr) {
    asm volatile("ldmatrix.sync.aligned.m8n8.x4.shared.b16 {%0,%1,%2,%3}, [%4];"
                 : "=r"(r[0]), "=r"(r[1]), "=r"(r[2]), "=r"(r[3]) : "r"(addr));
}
__device__ __forceinline__ void mma16816(float* c, const uint32_t* a, const uint32_t* b) {
    asm volatile("mma.sync.aligned.m16n8k16.row.col.f32.bf16.bf16.f32 "
                 "{%0,%1,%2,%3}, {%4,%5,%6,%7}, {%8,%9}, {%0,%1,%2,%3};"
                 : "+f"(c[0]), "+f"(c[1]), "+f"(c[2]), "+f"(c[3])
                 : "r"(a[0]), "r"(a[1]), "r"(a[2]), "r"(a[3]), "r"(b[0]), "r"(b[1]));
}

__device__ __forceinline__ void gemm192(float acc[2][12][4], uint32_t aBase, uint32_t wBase,
                                        uint32_t rowA, uint32_t rowB) {
#pragma unroll 2
    for (int kk = 0; kk < 12; kk++) {
        uint32_t af[2][4];
        uint32_t bfr[6][4];
        ldsm_x4(af[0], aBase + rowA + kk * 32);
        ldsm_x4(af[1], aBase + rowA + 16 * kRowB + kk * 32);
#pragma unroll
        for (int bj = 0; bj < 6; bj++)
            ldsm_x4(bfr[bj], wBase + rowB + bj * 16 * kRowB + kk * 32);
#pragma unroll
        for (int mi = 0; mi < 2; mi++)
#pragma unroll
            for (int nj = 0; nj < 12; nj++)
                mma16816(acc[mi][nj], af[mi], &bfr[nj >> 1][(nj & 1) * 2]);
    }
}

__global__ void __launch_bounds__(256, 1)
k_mlp_tc(const float* __restrict__ b1, const float* __restrict__ b2) {
    extern __shared__ char smc[];
    const int tid = threadIdx.x;
    const int lane = tid & 31;
    const int wid = tid >> 5;
    const int warp_m = wid & 3;
    const int warp_n = wid >> 2;
    const int grp = lane >> 2;
    const int tig = lane & 3;
    const int kb = blockIdx.y;
    const size_t m0 = (size_t)blockIdx.x * 128;

    const uint32_t su = (uint32_t)__cvta_generic_to_shared(smc);
    float* sB1 = (float*)(smc + kSmB1);
    float* sB2 = (float*)(smc + kSmB2);

    for (int idx = tid; idx < 96 * 128; idx += 256) {
        const int ci = idx >> 7;
        const int m = idx & 127;
        const float2 v = g_spec[((size_t)(kb * 96 + ci)) * kModes + m0 + m];
        __nv_bfloat162 hv;
        hv.x = __float2bfloat16(v.x);
        hv.y = __float2bfloat16(v.y);
        *(__nv_bfloat162*)(smc + kSmA + m * kRowB + ci * 4) = hv;
    }
    {
        const uint4* gw = (const uint4*)&g_wexp[kb][0][0][0];
        for (int idx = tid; idx < 192 * 24; idx += 256)
            *(uint4*)(smc + kSmW + (idx / 24) * kRowB + (idx % 24) * 16) = gw[idx];
    }
    for (int idx = tid; idx < 384; idx += 256) {
        if (idx < 192) sB1[idx] = b1[kb * 192 + idx];
        else sB2[idx - 192] = b2[kb * 192 + idx - 192];
    }
    __syncthreads();

    const uint32_t rowA = (uint32_t)((warp_m * 32 + (lane & 15)) * kRowB + ((lane >> 4) << 4));
    const uint32_t rowB = (uint32_t)((warp_n * 96 + (lane & 7) + ((lane >> 4) << 3)) * kRowB
                                     + ((lane & 8) ? 16 : 0));

    float acc[2][12][4];

    for (int mi = 0; mi < 2; mi++)
        for (int nj = 0; nj < 12; nj++) {
            const int n0 = warp_n * 96 + nj * 8 + 2 * tig;
            acc[mi][nj][0] = sB1[n0];
            acc[mi][nj][1] = sB1[n0 + 1];
            acc[mi][nj][2] = sB1[n0];
            acc[mi][nj][3] = sB1[n0 + 1];
        }
    gemm192(acc, su + kSmA, su + kSmW, rowA, rowB);

    for (int mi = 0; mi < 2; mi++)
        for (int nj = 0; nj < 12; nj++) {
            const int ml = warp_m * 32 + mi * 16 + grp;
            const int n0 = warp_n * 96 + nj * 8 + 2 * tig;
            __nv_bfloat162 hv;
            hv.x = __float2bfloat16(fmaxf(acc[mi][nj][0], 0.f));
            hv.y = __float2bfloat16(fmaxf(acc[mi][nj][1], 0.f));
            *(__nv_bfloat162*)(smc + kSmO + ml * kRowB + n0 * 2) = hv;
            hv.x = __float2bfloat16(fmaxf(acc[mi][nj][2], 0.f));
            hv.y = __float2bfloat16(fmaxf(acc[mi][nj][3], 0.f));
            *(__nv_bfloat162*)(smc + kSmO + (ml + 8) * kRowB + n0 * 2) = hv;
        }
    __syncthreads();

    {
        const uint4* gw = (const uint4*)&g_wexp[kb][1][0][0];
        for (int idx = tid; idx < 192 * 24; idx += 256)
            *(uint4*)(smc + kSmW + (idx / 24) * kRowB + (idx % 24) * 16) = gw[idx];
    }
    __syncthreads();

    for (int mi = 0; mi < 2; mi++)
        for (int nj = 0; nj < 12; nj++) {
            const int n0 = warp_n * 96 + nj * 8 + 2 * tig;
            acc[mi][nj][0] = sB2[n0];
            acc[mi][nj][1] = sB2[n0 + 1];
            acc[mi][nj][2] = sB2[n0];
            acc[mi][nj][3] = sB2[n0 + 1];
        }
    gemm192(acc, su + kSmO, su + kSmW, rowA, rowB);

    for (int mi = 0; mi < 2; mi++)
        for (int nj = 0; nj < 12; nj++) {
            const int ml = warp_m * 32 + mi * 16 + grp;
            const int n0 = warp_n * 96 + nj * 8 + 2 * tig;
            const int ch = kb * 96 + (n0 >> 1);
            float2 v;
            v.x = copysignf(fmaxf(fabsf(acc[mi][nj][0]) - kLam, 0.f), acc[mi][nj][0]);
            v.y = copysignf(fmaxf(fabsf(acc[mi][nj][1]) - kLam, 0.f), acc[mi][nj][1]);
            g_spec[(size_t)ch * kModes + m0 + ml] = v;
            v.x = copysignf(fmaxf(fabsf(acc[mi][nj][2]) - kLam, 0.f), acc[mi][nj][2]);
            v.y = copysignf(fmaxf(fabsf(acc[mi][nj][3]) - kLam, 0.f), acc[mi][nj][3]);
            g_spec[(size_t)ch * kModes + m0 + ml + 8] = v;
        }
}

// ---- inverse real FFT along W + residual ----
__global__ void k_inv_w(const float* __restrict__ x, float* __restrict__ out) {
    __shared__ float2 ivX[257];
    __shared__ float2 ivA[256];
    __shared__ float2 ivB[256];
    __shared__ float2 ivT[128];
    const int t = threadIdx.x;
    {
        float s, c;
        sincosf(kTwoPi * (float)t / 256.0f, &s, &c);
        ivT[t] = make_float2(c, s);
    }
    const size_t row = blockIdx.x;
    const float2* src = g_spec + row * kWC;
    {
        float2 v = src[t];
        if (t == 0) v.y = 0.f;
        ivX[t] = v;
        ivX[129 + t] = make_float2(0.f, 0.f);
        if (t == 0) ivX[128] = src[128];
    }
    __syncthreads();
    for (int half = 0; half < 2; half++) {
        const int kk = t + half * 128;
        const float2 Xk = ivX[kk];
        const float2 Xr = ivX[256 - kk];
        const float2 Xc = make_float2(Xr.x, -Xr.y);
        const float2 Ev = make_float2(0.5f * (Xk.x + Xc.x), 0.5f * (Xk.y + Xc.y));
        const float2 Dd = make_float2(0.5f * (Xk.x - Xc.x), 0.5f * (Xk.y - Xc.y));
        float s5, c5;
        sincosf(kTwoPi * (float)kk / 512.0f, &s5, &c5);
        const float2 Ov = cmul(make_float2(c5, s5), Dd);
        ivA[kk] = make_float2(Ev.x - Ov.y, Ev.y + Ov.x);
    }
    __syncthreads();

    float2* S = ivA;
    float2* D = ivB;
    for (int st = 0; st < 8; st++) {
        const int q = t & ((1 << st) - 1);
        const float2 w = ivT[t - q];
        const float2 a = S[t];
        const float2 b = S[t + 128];
        D[2 * t - q] = cadd(a, b);
        D[2 * t - q + (1 << st)] = cmul(csub(a, b), w);
        __syncthreads();
        float2* tmp = S; S = D; D = tmp;
    }
    const float2* xr = reinterpret_cast<const float2*>(x) + row * 256;
    float2* orow = reinterpret_cast<float2*>(out) + row * 256;
    {
        const float2 z0 = S[t];
        const float2 r0 = xr[t];
        orow[t] = make_float2(z0.x * kInvScale + r0.x, z0.y * kInvScale + r0.y);
        const float2 z1 = S[t + 128];
        const float2 r1 = xr[t + 128];
        orow[t + 128] = make_float2(z1.x * kInvScale + r1.x, z1.y * kInvScale + r1.y);
    }
}

extern "C" void kernel_launch(void* const* d_in, const int* in_sizes, int n_in,
                              void* d_out, int out_size) {
    (void)in_sizes; (void)n_in; (void)out_size;
    const float* x  = (const float*)d_in[0];
    const float* w1 = (const float*)d_in[1];
    const float* b1 = (const float*)d_in[2];
    const float* w2 = (const float*)d_in[3];
    const float* b2 = (const float*)d_in[4];
    float* out = (float*)d_out;

    cudaFuncSetAttribute(k_mlp_tc, cudaFuncAttributeMaxDynamicSharedMemorySize, kSmTotal);

    k_prep<<<(8 * 96 * 96 + 255) / 256, 256>>>(w1, w2);
    k_fwd_w<<<kNRows, 128>>>(x);

    dim3 gh(17, kCN);
    k_fft_h<-1><<<gh, 256>>>(kFwdScale);

    dim3 gm(kModes / 128, 8);
    k_mlp_tc<<<gm, 256, kSmTotal>>>(b1, b2);

    k_fft_h<1><<<gh, 256>>>(1.0f);

    k_inv_w<<<kNRows, 128>>>(x, out);
}

// round 6
// speedup vs baseline: 2.9860x; 1.3885x over previous
#include <cuda_runtime.h>
#include <cuda_bf16.h>
#include <math.h>
#include <stdint.h>

static constexpr int kCN = 768;
static constexpr int kHN = 256;
static constexpr int kWC = 129;
static constexpr int kModes = kHN * kWC;      // 33024
static constexpr int kNRows = kCN * kHN;      // 196608
static constexpr float kFwdScale = 0.00276213586400995f;  // 1/sqrt(256*512)
static constexpr float kInvScale = 0.00552427172801990f;  // sqrt(2)/256
static constexpr float kLam = 0.01f;
static constexpr float kTwoPi = 6.283185307179586f;

__device__ float2 g_spec[(size_t)kCN * kModes];
__device__ __nv_bfloat16 g_wexp[8][2][192][192];

__device__ __forceinline__ float2 cadd(float2 a, float2 b) { return make_float2(a.x + b.x, a.y + b.y); }
__device__ __forceinline__ float2 csub(float2 a, float2 b) { return make_float2(a.x - b.x, a.y - b.y); }
__device__ __forceinline__ float2 cmul(float2 a, float2 b) { return make_float2(a.x * b.x - a.y * b.y, a.x * b.y + a.y * b.x); }

// ---- weight expansion: complex w -> real 2x2 blocks, transposed [n][k] ----
__global__ void k_prep(const float* __restrict__ w1, const float* __restrict__ w2) {
    const int idx = blockIdx.x * 256 + threadIdx.x;  // (k*96+i)*96+o
    if (idx >= 8 * 96 * 96) return;
    const int kb = idx / 9216;
    const int rr = idx % 9216;
    const int ci = rr / 96;
    const int co = rr % 96;
    for (int L = 0; L < 2; L++) {
        const float* w = (L == 0) ? w1 : w2;
        const float re = w[idx * 2];
        const float im = w[idx * 2 + 1];
        __nv_bfloat16* W = &g_wexp[kb][L][0][0];
        W[(2 * co) * 192 + 2 * ci]         = __float2bfloat16(re);
        W[(2 * co) * 192 + 2 * ci + 1]     = __float2bfloat16(-im);
        W[(2 * co + 1) * 192 + 2 * ci]     = __float2bfloat16(im);
        W[(2 * co + 1) * 192 + 2 * ci + 1] = __float2bfloat16(re);
    }
}

// radix-4 Stockham stage helper: 64 butterflies over a 256-pt line.
// SIGN=-1 forward, +1 inverse. tw[k] = exp(SIGN*2*pi*i*k/256).
template <int SIGN>
__device__ __forceinline__ void r4_stage(const float2* S, float2* D, const float2* tw,
                                         int t, int st) {
    const int L = 1 << (2 * st);
    const int q = t & (L - 1);
    const int base = t - q;
    const float2 a0 = S[t];
    const float2 a1 = S[t + 64];
    const float2 a2 = S[t + 128];
    const float2 a3 = S[t + 192];
    const float2 s02 = cadd(a0, a2);
    const float2 d02 = csub(a0, a2);
    const float2 s13 = cadd(a1, a3);
    const float2 d13 = csub(a1, a3);
    const float2 w1 = tw[base];
    const float2 w2 = tw[(2 * base) & 255];
    const float2 w3 = tw[(3 * base) & 255];
    const int pos = 4 * base + q;
    D[pos] = cadd(s02, s13);
    float2 u1 = make_float2(d02.x - (float)SIGN * d13.y, d02.y + (float)SIGN * d13.x);
    float2 u3 = make_float2(d02.x + (float)SIGN * d13.y, d02.y - (float)SIGN * d13.x);
    D[pos + L] = cmul(u1, w1);
    D[pos + 2 * L] = cmul(csub(s02, s13), w2);
    D[pos + 3 * L] = cmul(u3, w3);
}

// ---- forward real FFT along W (512) via 256-pt pack trick, radix-4 ----
__global__ void k_fwd_w(const float* __restrict__ x) {
    __shared__ float2 fwA[2][256];
    __shared__ float2 fwB[2][256];
    __shared__ float2 fwT[256];
    const int tid = threadIdx.x;  // 128
    const int r = tid >> 6;
    const int t = tid & 63;
    for (int i = tid; i < 256; i += 128) {
        float s, c;
        sincosf(-kTwoPi * (float)i / 256.0f, &s, &c);
        fwT[i] = make_float2(c, s);
    }
    const size_t row = (size_t)blockIdx.x * 2 + r;
    const float2* xr = reinterpret_cast<const float2*>(x) + row * 256;
    fwA[r][t] = xr[t];
    fwA[r][t + 64] = xr[t + 64];
    fwA[r][t + 128] = xr[t + 128];
    fwA[r][t + 192] = xr[t + 192];
    __syncthreads();

    float2* S = fwA[r];
    float2* D = fwB[r];
    for (int st = 0; st < 4; st++) {
        r4_stage<-1>(S, D, fwT, t, st);
        __syncthreads();
        float2* tmp = S; S = D; D = tmp;
    }
    // S == fwA[r]; Hermitian unpack for k = t, t+64 (+ thread 0 does 128)
    float2* dst = g_spec + row * kWC;
    for (int h = 0; h < 2; h++) {
        const int k = t + 64 * h;
        const float2 Zk = S[k];
        const float2 Zr = S[(256 - k) & 255];
        const float2 Zc = make_float2(Zr.x, -Zr.y);
        float s5, c5;
        sincosf(-kTwoPi * (float)k / 512.0f, &s5, &c5);
        const float2 ed = cmul(make_float2(c5, s5), csub(Zk, Zc));
        const float2 su = cadd(Zk, Zc);
        dst[k] = make_float2(0.5f * (su.x + ed.y), 0.5f * (su.y - ed.x));
    }
    if (t == 0) {
        const float2 Zk = S[128];
        const float2 Zc = make_float2(Zk.x, -Zk.y);
        const float2 ed = cmul(make_float2(0.f, -1.f), csub(Zk, Zc));
        const float2 su = cadd(Zk, Zc);
        dst[128] = make_float2(0.5f * (su.x + ed.y), 0.5f * (su.y - ed.x));
    }
}

// ---- 256-pt complex FFT along H over columns of g_spec, radix-4 ----
template <int SIGN>
__global__ void k_fft_h(float scale) {
    __shared__ float2 hA[8][257];
    __shared__ float2 hB[8][257];
    __shared__ float2 hT[256];
    const int tid = threadIdx.x;  // 256
    {
        float s, c;
        sincosf((float)SIGN * kTwoPi * (float)tid / 256.0f, &s, &c);
        hT[tid] = make_float2(c, s);
    }
    const int ch = blockIdx.y;
    const int y0 = blockIdx.x * 8;
    const int yc = tid & 7;
    const int hh = tid >> 3;
    const int y = y0 + yc;
    for (int i = 0; i < 8; i++) {
        const int h = hh + i * 32;
        float2 v = make_float2(0.f, 0.f);
        if (y < kWC) v = g_spec[((size_t)ch * kHN + h) * kWC + y];
        hA[yc][h] = v;
    }
    __syncthreads();

    float2(*S)[257] = hA;
    float2(*D)[257] = hB;
    for (int st = 0; st < 4; st++) {
        for (int i = 0; i < 2; i++) {
            const int idx = tid + (i << 8);  // 0..511
            const int col = idx >> 6;        // 0..7
            const int t = idx & 63;
            r4_stage<SIGN>(S[col], D[col], hT, t, st);
        }
        __syncthreads();
        float2(*tmp)[257] = S; S = D; D = tmp;
    }
    if (y < kWC) {
        for (int i = 0; i < 8; i++) {
            const int h = hh + i * 32;
            const float2 v = S[yc][h];
            g_spec[((size_t)ch * kHN + h) * kWC + y] = make_float2(v.x * scale, v.y * scale);
        }
    }
}

// ---- tensor-core MLP: 512 threads, M-tile 256, O reuses A buffer ----
static constexpr int kRowB = 400;
static constexpr int kSmA = 0;               // 256 rows * 400 = 102400 (A, then O)
static constexpr int kSmW = 102400;          // 192 rows * 400 = 76800
static constexpr int kSmB1 = 179200;
static constexpr int kSmB2 = 179968;
static constexpr int kSmTotal = 180736;

__device__ __forceinline__ void ldsm_x4(uint32_t* r, uint32_t addr) {
    asm volatile("ldmatrix.sync.aligned.m8n8.x4.shared.b16 {%0,%1,%2,%3}, [%4];"
                 : "=r"(r[0]), "=r"(r[1]), "=r"(r[2]), "=r"(r[3]) : "r"(addr));
}
__device__ __forceinline__ void mma16816(float* c, const uint32_t* a, const uint32_t* b) {
    asm volatile("mma.sync.aligned.m16n8k16.row.col.f32.bf16.bf16.f32 "
                 "{%0,%1,%2,%3}, {%4,%5,%6,%7}, {%8,%9}, {%0,%1,%2,%3};"
                 : "+f"(c[0]), "+f"(c[1]), "+f"(c[2]), "+f"(c[3])
                 : "r"(a[0]), "r"(a[1]), "r"(a[2]), "r"(a[3]), "r"(b[0]), "r"(b[1]));
}

__device__ __forceinline__ void gemm192(float acc[2][12][4], uint32_t aBase, uint32_t wBase,
                                        uint32_t rowA, uint32_t rowB) {
#pragma unroll 2
    for (int kk = 0; kk < 12; kk++) {
        uint32_t af[2][4];
        uint32_t bfr[6][4];
        ldsm_x4(af[0], aBase + rowA + kk * 32);
        ldsm_x4(af[1], aBase + rowA + 16 * kRowB + kk * 32);
#pragma unroll
        for (int bj = 0; bj < 6; bj++)
            ldsm_x4(bfr[bj], wBase + rowB + bj * 16 * kRowB + kk * 32);
#pragma unroll
        for (int mi = 0; mi < 2; mi++)
#pragma unroll
            for (int nj = 0; nj < 12; nj++)
                mma16816(acc[mi][nj], af[mi], &bfr[nj >> 1][(nj & 1) * 2]);
    }
}

__global__ void __launch_bounds__(512, 1)
k_mlp_tc(const float* __restrict__ b1, const float* __restrict__ b2) {
    extern __shared__ char smc[];
    const int tid = threadIdx.x;
    const int lane = tid & 31;
    const int wid = tid >> 5;
    const int warp_m = wid & 7;       // 0..7 -> M offset *32
    const int warp_n = wid >> 3;      // 0..1 -> N offset *96
    const int grp = lane >> 2;
    const int tig = lane & 3;
    const int kb = blockIdx.y;
    const size_t m0 = (size_t)blockIdx.x * 256;

    const uint32_t su = (uint32_t)__cvta_generic_to_shared(smc);
    float* sB1 = (float*)(smc + kSmB1);
    float* sB2 = (float*)(smc + kSmB2);

    for (int idx = tid; idx < 96 * 256; idx += 512) {
        const int ci = idx >> 8;
        const int m = idx & 255;
        const float2 v = g_spec[((size_t)(kb * 96 + ci)) * kModes + m0 + m];
        __nv_bfloat162 hv;
        hv.x = __float2bfloat16(v.x);
        hv.y = __float2bfloat16(v.y);
        *(__nv_bfloat162*)(smc + kSmA + m * kRowB + ci * 4) = hv;
    }
    {
        const uint4* gw = (const uint4*)&g_wexp[kb][0][0][0];
        for (int idx = tid; idx < 192 * 24; idx += 512)
            *(uint4*)(smc + kSmW + (idx / 24) * kRowB + (idx % 24) * 16) = gw[idx];
    }
    for (int idx = tid; idx < 384; idx += 512) {
        if (idx < 192) sB1[idx] = b1[kb * 192 + idx];
        else sB2[idx - 192] = b2[kb * 192 + idx - 192];
    }
    __syncthreads();

    const uint32_t rowA = (uint32_t)((warp_m * 32 + (lane & 15)) * kRowB + ((lane >> 4) << 4));
    const uint32_t rowB = (uint32_t)((warp_n * 96 + (lane & 7) + ((lane >> 4) << 3)) * kRowB
                                     + ((lane & 8) ? 16 : 0));

    float acc[2][12][4];

    for (int mi = 0; mi < 2; mi++)
        for (int nj = 0; nj < 12; nj++) {
            const int n0 = warp_n * 96 + nj * 8 + 2 * tig;
            acc[mi][nj][0] = sB1[n0];
            acc[mi][nj][1] = sB1[n0 + 1];
            acc[mi][nj][2] = sB1[n0];
            acc[mi][nj][3] = sB1[n0 + 1];
        }
    gemm192(acc, su + kSmA, su + kSmW, rowA, rowB);
    __syncthreads();   // all warps done reading A before O overwrites it

    for (int mi = 0; mi < 2; mi++)
        for (int nj = 0; nj < 12; nj++) {
            const int ml = warp_m * 32 + mi * 16 + grp;
            const int n0 = warp_n * 96 + nj * 8 + 2 * tig;
            __nv_bfloat162 hv;
            hv.x = __float2bfloat16(fmaxf(acc[mi][nj][0], 0.f));
            hv.y = __float2bfloat16(fmaxf(acc[mi][nj][1], 0.f));
            *(__nv_bfloat162*)(smc + kSmA + ml * kRowB + n0 * 2) = hv;
            hv.x = __float2bfloat16(fmaxf(acc[mi][nj][2], 0.f));
            hv.y = __float2bfloat16(fmaxf(acc[mi][nj][3], 0.f));
            *(__nv_bfloat162*)(smc + kSmA + (ml + 8) * kRowB + n0 * 2) = hv;
        }
    {
        const uint4* gw = (const uint4*)&g_wexp[kb][1][0][0];
        for (int idx = tid; idx < 192 * 24; idx += 512)
            *(uint4*)(smc + kSmW + (idx / 24) * kRowB + (idx % 24) * 16) = gw[idx];
    }
    __syncthreads();

    for (int mi = 0; mi < 2; mi++)
        for (int nj = 0; nj < 12; nj++) {
            const int n0 = warp_n * 96 + nj * 8 + 2 * tig;
            acc[mi][nj][0] = sB2[n0];
            acc[mi][nj][1] = sB2[n0 + 1];
            acc[mi][nj][2] = sB2[n0];
            acc[mi][nj][3] = sB2[n0 + 1];
        }
    gemm192(acc, su + kSmA, su + kSmW, rowA, rowB);

    for (int mi = 0; mi < 2; mi++)
        for (int nj = 0; nj < 12; nj++) {
            const int ml = warp_m * 32 + mi * 16 + grp;
            const int n0 = warp_n * 96 + nj * 8 + 2 * tig;
            const int ch = kb * 96 + (n0 >> 1);
            float2 v;
            v.x = copysignf(fmaxf(fabsf(acc[mi][nj][0]) - kLam, 0.f), acc[mi][nj][0]);
            v.y = copysignf(fmaxf(fabsf(acc[mi][nj][1]) - kLam, 0.f), acc[mi][nj][1]);
            g_spec[(size_t)ch * kModes + m0 + ml] = v;
            v.x = copysignf(fmaxf(fabsf(acc[mi][nj][2]) - kLam, 0.f), acc[mi][nj][2]);
            v.y = copysignf(fmaxf(fabsf(acc[mi][nj][3]) - kLam, 0.f), acc[mi][nj][3]);
            g_spec[(size_t)ch * kModes + m0 + ml + 8] = v;
        }
}

// ---- inverse real FFT along W + residual, radix-4, 2 rows/CTA ----
__global__ void k_inv_w(const float* __restrict__ x, float* __restrict__ out) {
    __shared__ float2 ivX[2][257];
    __shared__ float2 ivA[2][256];
    __shared__ float2 ivB[2][256];
    __shared__ float2 ivT[256];
    const int tid = threadIdx.x;  // 128
    const int r = tid >> 6;
    const int t = tid & 63;
    for (int i = tid; i < 256; i += 128) {
        float s, c;
        sincosf(kTwoPi * (float)i / 256.0f, &s, &c);
        ivT[i] = make_float2(c, s);
    }
    const size_t row = (size_t)blockIdx.x * 2 + r;
    const float2* src = g_spec + row * kWC;
    {
        float2 v = src[t];
        if (t == 0) v.y = 0.f;          // c2r drops Im of bin 0
        ivX[r][t] = v;
        ivX[r][t + 64] = src[t + 64];
        ivX[r][129 + t] = make_float2(0.f, 0.f);
        ivX[r][193 + t] = make_float2(0.f, 0.f);
        if (t == 0) ivX[r][128] = src[128];
    }
    __syncthreads();
    for (int h = 0; h < 4; h++) {
        const int kk = t + 64 * h;
        const float2 Xk = ivX[r][kk];
        const float2 Xr = ivX[r][256 - kk];
        const float2 Xc = make_float2(Xr.x, -Xr.y);
        const float2 Ev = make_float2(0.5f * (Xk.x + Xc.x), 0.5f * (Xk.y + Xc.y));
        const float2 Dd = make_float2(0.5f * (Xk.x - Xc.x), 0.5f * (Xk.y - Xc.y));
        float s5, c5;
        sincosf(kTwoPi * (float)kk / 512.0f, &s5, &c5);
        const float2 Ov = cmul(make_float2(c5, s5), Dd);
        ivA[r][kk] = make_float2(Ev.x - Ov.y, Ev.y + Ov.x);
    }
    __syncthreads();

    float2* S = ivA[r];
    float2* D = ivB[r];
    for (int st = 0; st < 4; st++) {
        r4_stage<1>(S, D, ivT, t, st);
        __syncthreads();
        float2* tmp = S; S = D; D = tmp;
    }
    const float2* xr = reinterpret_cast<const float2*>(x) + row * 256;
    float2* orow = reinterpret_cast<float2*>(out) + row * 256;
    for (int h = 0; h < 4; h++) {
        const int n = t + 64 * h;
        const float2 z = S[n];
        const float2 rv = xr[n];
        orow[n] = make_float2(z.x * kInvScale + rv.x, z.y * kInvScale + rv.y);
    }
}

extern "C" void kernel_launch(void* const* d_in, const int* in_sizes, int n_in,
                              void* d_out, int out_size) {
    (void)in_sizes; (void)n_in; (void)out_size;
    const float* x  = (const float*)d_in[0];
    const float* w1 = (const float*)d_in[1];
    const float* b1 = (const float*)d_in[2];
    const float* w2 = (const float*)d_in[3];
    const float* b2 = (const float*)d_in[4];
    float* out = (float*)d_out;

    cudaFuncSetAttribute(k_mlp_tc, cudaFuncAttributeMaxDynamicSharedMemorySize, kSmTotal);

    k_prep<<<(8 * 96 * 96 + 255) / 256, 256>>>(w1, w2);
    k_fwd_w<<<kNRows / 2, 128>>>(x);

    dim3 gh(17, kCN);
    k_fft_h<-1><<<gh, 256>>>(kFwdScale);

    dim3 gm(kModes / 256, 8);
    k_mlp_tc<<<gm, 512, kSmTotal>>>(b1, b2);

    k_fft_h<1><<<gh, 256>>>(1.0f);

    k_inv_w<<<kNRows / 2, 128>>>(x, out);
}